// round 15
// baseline (speedup 1.0000x reference)
#include <cuda_runtime.h>
#include <math.h>

#define EPS 1e-20f
#define Bn 4
#define Cn 32
#define On 32
#define Hn 256
#define Wn 256
#define HOn 128
#define WOn 128
#define HWO (HOn*WOn)      /* 16384 */
#define KK 9

// -------- device scratch (no allocations allowed) --------
__device__ float2 g_PQ[Bn*Cn*HWO];            // (cgx_sp*gx_sp, cgx_sp) interleaved
__device__ unsigned long long g_cw2[Cn*On];   // [c][o] softplus(cw) packed {w,w}
__device__ float g_invS2_4;                   // 0.25/(sum cw + eps)

__device__ __forceinline__ float softplusf(float x) {
    return fmaxf(x, 0.0f) + log1pf(expf(-fabsf(x)));
}

// packed f32x2 FMA / ADD (sm_103a — only reachable via PTX)
#define FMA2(acc, a, b) \
    asm("fma.rn.f32x2 %0, %1, %2, %3;" : "=l"(acc) : "l"(a), "l"(b), "l"(acc))
#define ADD2(dst, a, b) \
    asm("add.rn.f32x2 %0, %1, %2;" : "=l"(dst) : "l"(a), "l"(b))

// -------- kernel 1: stage1 + spatial (per (b,c), 4 output rows per block) --------
// (byte-exact round-7 kernel — best measured 34.8us; bc-fast grid order)
// Stage1 exact simplification (reference's pad_r/pad_l are edge-zero masks):
//   cgx_from_ds = s^3 * cd^2 for 0<x<W-1, else 0;  gx_from_ds term contributes 0.
//   U = wp*cgx*gx ;  V = wp*cgx + cgx_from_ds
// Spatial: nom = sum_k sw_k*sprod_k*U_k/(wp+1);  den = sum_k sw_k*sprod_k*V_k/(wp+1)
//   P = nom/(S+eps) ;  Q = den/(S+eps)
__global__ __launch_bounds__(256) void spatial_kernel(
    const float* __restrict__ s_in, const float* __restrict__ cd,
    const float* __restrict__ gx,   const float* __restrict__ cgx,
    const float* __restrict__ sprod,
    const float* __restrict__ w_prop, const float* __restrict__ spatial_weight,
    const float* __restrict__ channel_weight)
{
    // parity-split tile, U,V packed: taps (2wo-1, 2wo, 2wo+1) -> odd[wo], even[wo], odd[wo+1]
    __shared__ float2 sUVe[9][128];
    __shared__ float2 sUVo[9][132];   // [0] = zero pad (x = -1)
    __shared__ float  s_sw[KK];
    __shared__ float  s_S;
    __shared__ float  s_cwsum[8];

    const int bc  = blockIdx.x;          // b*Cn + c
    const int c   = bc & (Cn - 1);
    const int ho0 = blockIdx.y * 4;
    const int ir0 = 2 * ho0 - 1;
    const int t   = threadIdx.x;

    const float wp = softplusf(__ldg(&w_prop[c]));

    // warp 0: sum of all 288 softplus(spatial_weight) via shuffle
    if (t < 32) {
        float acc = 0.0f;
        #pragma unroll
        for (int k = 0; k < KK; k++)
            acc += softplusf(__ldg(&spatial_weight[t * KK + k]));
        #pragma unroll
        for (int off = 16; off > 0; off >>= 1)
            acc += __shfl_xor_sync(0xffffffffu, acc, off);
        if (t == 0) s_S = acc;
    }
    if (t >= 32 && t < 32 + KK)
        s_sw[t - 32] = softplusf(__ldg(&spatial_weight[c * KK + (t - 32)]));
    if (t >= 64 && t < 64 + 9)
        sUVo[t - 64][0] = make_float2(0.0f, 0.0f);

    // block (0,0) additionally pre-packs channel weights for the channel kernel
    const bool cwblk = (blockIdx.x == 0) && (blockIdx.y == 0);
    if (cwblk) {
        float partial = 0.0f;
        #pragma unroll
        for (int i = t; i < Cn * On; i += 256) {
            const int o = i >> 5, cc = i & 31;
            const float w = softplusf(__ldg(&channel_weight[i]));  // i = o*Cn + cc
            const unsigned wu = __float_as_uint(w);
            g_cw2[cc * On + o] = ((unsigned long long)wu << 32) | wu;
            partial += w;
        }
        #pragma unroll
        for (int off = 16; off > 0; off >>= 1)
            partial += __shfl_xor_sync(0xffffffffu, partial, off);
        if ((t & 31) == 0) s_cwsum[t >> 5] = partial;
    }

    const size_t plane = (size_t)bc * (Hn * Wn);

    // ---- stage U,V for 9 input rows x 256 cols (float4-coalesced, streaming) ----
    for (int idx = t; idx < 9 * 64; idx += 256) {
        const int r  = idx >> 6;
        const int g4 = idx & 63;
        const int ir = ir0 + r;
        float u[4], v[4];
        if (ir >= 0 && ir < Hn) {
            const size_t base = plane + (size_t)ir * Wn + g4 * 4;
            const float4 sx  = __ldcs((const float4*)(s_in + base));
            const float4 cdx = __ldcs((const float4*)(cd   + base));
            const float4 gxx = __ldcs((const float4*)(gx   + base));
            const float4 cgv = __ldcs((const float4*)(cgx  + base));
            const float se[4]  = {sx.x,  sx.y,  sx.z,  sx.w};
            const float cde[4] = {cdx.x, cdx.y, cdx.z, cdx.w};
            const float ge[4]  = {gxx.x, gxx.y, gxx.z, gxx.w};
            const float cge[4] = {cgv.x, cgv.y, cgv.z, cgv.w};
            #pragma unroll
            for (int e = 0; e < 4; e++) {
                const int x = g4 * 4 + e;
                const float cgds = (x == 0 || x == Wn - 1)
                                 ? 0.0f
                                 : se[e] * se[e] * se[e] * cde[e] * cde[e];
                u[e] = wp * cge[e] * ge[e];
                v[e] = wp * cge[e] + cgds;
            }
        } else {
            #pragma unroll
            for (int e = 0; e < 4; e++) { u[e] = 0.0f; v[e] = 0.0f; }
        }
        // parity-split store: even x -> [x/2], odd x -> [x/2 + 1]
        sUVe[r][2 * g4]     = make_float2(u[0], v[0]);
        sUVo[r][2 * g4 + 1] = make_float2(u[1], v[1]);
        sUVe[r][2 * g4 + 1] = make_float2(u[2], v[2]);
        sUVo[r][2 * g4 + 2] = make_float2(u[3], v[3]);
    }
    __syncthreads();

    if (cwblk && t == 0) {
        g_invS2_4 = 0.25f / (s_cwsum[0] + s_cwsum[1] + s_cwsum[2] + s_cwsum[3]
                           + s_cwsum[4] + s_cwsum[5] + s_cwsum[6] + s_cwsum[7] + EPS);
    }

    const float scale = (1.0f / (wp + 1.0f)) * (1.0f / (s_S + EPS));

    // ---- spatial 3x3 stride-2 reduce (2 output pixels per thread) ----
    const int wo = t & 127;
    const int hb = t >> 7;            // 0 or 1
    #pragma unroll
    for (int it = 0; it < 2; ++it) {
        const int hloc = hb + it * 2;
        const int ho   = ho0 + hloc;
        float nom = 0.0f, den = 0.0f;
        const size_t spbase = (size_t)bc * KK * HWO + (size_t)ho * WOn + wo;
        #pragma unroll
        for (int i = 0; i < 3; i++) {
            const int r = 2 * hloc + i;
            const float sp0 = __ldcs(&sprod[spbase + (size_t)(i * 3 + 0) * HWO]);
            const float sp1 = __ldcs(&sprod[spbase + (size_t)(i * 3 + 1) * HWO]);
            const float sp2 = __ldcs(&sprod[spbase + (size_t)(i * 3 + 2) * HWO]);
            const float w0 = s_sw[i * 3 + 0] * sp0;   // x = 2wo-1 (odd)
            const float w1 = s_sw[i * 3 + 1] * sp1;   // x = 2wo   (even)
            const float w2 = s_sw[i * 3 + 2] * sp2;   // x = 2wo+1 (odd)
            const float2 a = sUVo[r][wo];
            const float2 b = sUVe[r][wo];
            const float2 d = sUVo[r][wo + 1];
            nom += w0 * a.x + w1 * b.x + w2 * d.x;
            den += w0 * a.y + w1 * b.y + w2 * d.y;
        }
        const size_t oidx = (size_t)bc * HWO + (size_t)ho * WOn + wo;
        g_PQ[oidx] = make_float2(nom * scale, den * scale);
    }
}

// -------- kernel 2: 1x1 channel mix, channel-split across lane pairs --------
// Lane pair (even, odd) shares one pixel: even accumulates channels 0-15,
// odd channels 16-31; u64 shfl_xor(1) + add.rn.f32x2 merges. 262K threads
// (55 warps/SM) with NO extra PQ traffic (og-split 2 preserved).
__global__ __launch_bounds__(128) void channel_kernel(
    const float* __restrict__ bias, float* __restrict__ out)
{
    __shared__ ulonglong2 scw[Cn * 8];   // [cc][op], 2 packed weights per entry
    __shared__ float sbias[16];
    const int t   = threadIdx.x;
    const int og0 = (blockIdx.x & 1) * 16;       // og half

    #pragma unroll
    for (int i = t; i < Cn * 8; i += 128) {
        const int cc = i >> 3, op = i & 7;
        scw[i] = make_ulonglong2(g_cw2[cc * On + og0 + 2 * op],
                                 g_cw2[cc * On + og0 + 2 * op + 1]);
    }
    if (t < 16) sbias[t] = __ldg(&bias[og0 + t]);
    __syncthreads();
    const float invS2_4 = g_invS2_4;

    const int px = (blockIdx.x >> 1) * 64 + (t >> 1);  // lane pair shares pixel
    const int b  = px >> 14;             // / HWO (uniform per block: 64 | HWO)
    const int hw = px & (HWO - 1);
    const int c0 = (t & 1) * 16;         // channel half for this lane

    const unsigned long long* PQ =
        (const unsigned long long*)g_PQ
        + (size_t)b * Cn * HWO + (size_t)c0 * HWO + hw;

    unsigned long long acc[16];
    #pragma unroll
    for (int oo = 0; oo < 16; oo++) acc[oo] = 0ull;

    // depth-2 pipeline over 4 chunks of 4 channels (16 channels per lane)
    unsigned long long buf[2][4];
    #pragma unroll
    for (int j = 0; j < 4; j++) buf[0][j] = PQ[(size_t)j * HWO];
    #pragma unroll
    for (int j = 0; j < 4; j++) buf[1][j] = PQ[(size_t)(4 + j) * HWO];

    #pragma unroll
    for (int cg = 0; cg < 4; cg++) {
        const int cc0 = cg * 4;
        const int cur = cg & 1;
        #pragma unroll
        for (int j = 0; j < 4; j++) {
            const unsigned long long p = buf[cur][j];
            #pragma unroll
            for (int op = 0; op < 8; op++) {
                const ulonglong2 ww = scw[(c0 + cc0 + j) * 8 + op];  // LDS.128
                FMA2(acc[2 * op],     p, ww.x);
                FMA2(acc[2 * op + 1], p, ww.y);
            }
        }
        if (cg < 2) {
            #pragma unroll
            for (int j = 0; j < 4; j++)
                buf[cur][j] = PQ[(size_t)(cc0 + 8 + j) * HWO];
        }
    }

    // merge channel halves across the lane pair (packed f32x2 add)
    #pragma unroll
    for (int oo = 0; oo < 16; oo++) {
        const unsigned long long other = __shfl_xor_sync(0xffffffffu, acc[oo], 1);
        ADD2(acc[oo], acc[oo], other);
    }

    // each lane stores 8 of the 16 outputs (even: 0-7, odd: 8-15)
    const int ooB = (t & 1) * 8;
    const size_t obase = (size_t)b * On * HWO + (size_t)og0 * HWO + hw;
    const size_t half  = (size_t)Bn * On * HWO;
    #pragma unroll
    for (int k = 0; k < 8; k++) {
        const int oo = ooB + k;
        const float n = __uint_as_float((unsigned)acc[oo]);
        const float d = __uint_as_float((unsigned)(acc[oo] >> 32));
        out[obase + (size_t)oo * HWO]        =
            (__fdividef(n, d + EPS) + sbias[oo]) * 2.0f;
        out[half + obase + (size_t)oo * HWO] = d * invS2_4;
    }
}

extern "C" void kernel_launch(void* const* d_in, const int* in_sizes, int n_in,
                              void* d_out, int out_size) {
    // metadata order: d, cd, s, cs, gx, cgx, s_prod_roll,
    //                 w_prop, spatial_weight, channel_weight, bias
    // (d and cs are provably unused — see stage1 simplification)
    const float* cd_p    = (const float*)d_in[1];
    const float* s_p     = (const float*)d_in[2];
    const float* gx_p    = (const float*)d_in[4];
    const float* cgx_p   = (const float*)d_in[5];
    const float* sprod_p = (const float*)d_in[6];
    const float* wprop_p = (const float*)d_in[7];
    const float* sw_p    = (const float*)d_in[8];
    const float* cw_p    = (const float*)d_in[9];
    const float* bias_p  = (const float*)d_in[10];

    dim3 gA(Bn * Cn, 32);            // bc-fast block order (best measured)
    spatial_kernel<<<gA, 256>>>(s_p, cd_p, gx_p, cgx_p, sprod_p,
                                wprop_p, sw_p, cw_p);

    // 65536 px x 2 og-halves x 2 ch-halves / 128 threads = 2048 blocks
    channel_kernel<<<2048, 128>>>(bias_p, (float*)d_out);
}

// round 16
// speedup vs baseline: 1.0727x; 1.0727x over previous
#include <cuda_runtime.h>
#include <math.h>

#define EPS 1e-20f
#define Bn 4
#define Cn 32
#define On 32
#define Hn 256
#define Wn 256
#define HOn 128
#define WOn 128
#define HWO (HOn*WOn)      /* 16384 */
#define KK 9

// -------- device scratch (no allocations allowed) --------
__device__ float2 g_PQ[Bn*Cn*HWO];            // (cgx_sp*gx_sp, cgx_sp) interleaved
__device__ unsigned long long g_cw2[Cn*On];   // [c][o] softplus(cw) packed {w,w}
__device__ float g_invS2_4;                   // 0.25/(sum cw + eps)

__device__ __forceinline__ float softplusf(float x) {
    return fmaxf(x, 0.0f) + log1pf(expf(-fabsf(x)));
}

// packed f32x2 FMA (sm_103a FFMA2 — only reachable via PTX)
#define FMA2(acc, a, b) \
    asm("fma.rn.f32x2 %0, %1, %2, %3;" : "=l"(acc) : "l"(a), "l"(b), "l"(acc))

// -------- kernel 1: stage1 + spatial (per (b,c), 4 output rows per block) --------
// (byte-exact round-7 kernel — best measured 34.8us; bc-fast grid order)
// Stage1 exact simplification (reference's pad_r/pad_l are edge-zero masks):
//   cgx_from_ds = s^3 * cd^2 for 0<x<W-1, else 0;  gx_from_ds term contributes 0.
//   U = wp*cgx*gx ;  V = wp*cgx + cgx_from_ds
// Spatial: nom = sum_k sw_k*sprod_k*U_k/(wp+1);  den = sum_k sw_k*sprod_k*V_k/(wp+1)
//   P = nom/(S+eps) ;  Q = den/(S+eps)
__global__ __launch_bounds__(256) void spatial_kernel(
    const float* __restrict__ s_in, const float* __restrict__ cd,
    const float* __restrict__ gx,   const float* __restrict__ cgx,
    const float* __restrict__ sprod,
    const float* __restrict__ w_prop, const float* __restrict__ spatial_weight,
    const float* __restrict__ channel_weight)
{
    // parity-split tile, U,V packed: taps (2wo-1, 2wo, 2wo+1) -> odd[wo], even[wo], odd[wo+1]
    __shared__ float2 sUVe[9][128];
    __shared__ float2 sUVo[9][132];   // [0] = zero pad (x = -1)
    __shared__ float  s_sw[KK];
    __shared__ float  s_S;
    __shared__ float  s_cwsum[8];

    const int bc  = blockIdx.x;          // b*Cn + c
    const int c   = bc & (Cn - 1);
    const int ho0 = blockIdx.y * 4;
    const int ir0 = 2 * ho0 - 1;
    const int t   = threadIdx.x;

    const float wp = softplusf(__ldg(&w_prop[c]));

    // warp 0: sum of all 288 softplus(spatial_weight) via shuffle
    if (t < 32) {
        float acc = 0.0f;
        #pragma unroll
        for (int k = 0; k < KK; k++)
            acc += softplusf(__ldg(&spatial_weight[t * KK + k]));
        #pragma unroll
        for (int off = 16; off > 0; off >>= 1)
            acc += __shfl_xor_sync(0xffffffffu, acc, off);
        if (t == 0) s_S = acc;
    }
    if (t >= 32 && t < 32 + KK)
        s_sw[t - 32] = softplusf(__ldg(&spatial_weight[c * KK + (t - 32)]));
    if (t >= 64 && t < 64 + 9)
        sUVo[t - 64][0] = make_float2(0.0f, 0.0f);

    // block (0,0) additionally pre-packs channel weights for the channel kernel
    const bool cwblk = (blockIdx.x == 0) && (blockIdx.y == 0);
    if (cwblk) {
        float partial = 0.0f;
        #pragma unroll
        for (int i = t; i < Cn * On; i += 256) {
            const int o = i >> 5, cc = i & 31;
            const float w = softplusf(__ldg(&channel_weight[i]));  // i = o*Cn + cc
            const unsigned wu = __float_as_uint(w);
            g_cw2[cc * On + o] = ((unsigned long long)wu << 32) | wu;
            partial += w;
        }
        #pragma unroll
        for (int off = 16; off > 0; off >>= 1)
            partial += __shfl_xor_sync(0xffffffffu, partial, off);
        if ((t & 31) == 0) s_cwsum[t >> 5] = partial;
    }

    const size_t plane = (size_t)bc * (Hn * Wn);

    // ---- stage U,V for 9 input rows x 256 cols (float4-coalesced, streaming) ----
    for (int idx = t; idx < 9 * 64; idx += 256) {
        const int r  = idx >> 6;
        const int g4 = idx & 63;
        const int ir = ir0 + r;
        float u[4], v[4];
        if (ir >= 0 && ir < Hn) {
            const size_t base = plane + (size_t)ir * Wn + g4 * 4;
            const float4 sx  = __ldcs((const float4*)(s_in + base));
            const float4 cdx = __ldcs((const float4*)(cd   + base));
            const float4 gxx = __ldcs((const float4*)(gx   + base));
            const float4 cgv = __ldcs((const float4*)(cgx  + base));
            const float se[4]  = {sx.x,  sx.y,  sx.z,  sx.w};
            const float cde[4] = {cdx.x, cdx.y, cdx.z, cdx.w};
            const float ge[4]  = {gxx.x, gxx.y, gxx.z, gxx.w};
            const float cge[4] = {cgv.x, cgv.y, cgv.z, cgv.w};
            #pragma unroll
            for (int e = 0; e < 4; e++) {
                const int x = g4 * 4 + e;
                const float cgds = (x == 0 || x == Wn - 1)
                                 ? 0.0f
                                 : se[e] * se[e] * se[e] * cde[e] * cde[e];
                u[e] = wp * cge[e] * ge[e];
                v[e] = wp * cge[e] + cgds;
            }
        } else {
            #pragma unroll
            for (int e = 0; e < 4; e++) { u[e] = 0.0f; v[e] = 0.0f; }
        }
        // parity-split store: even x -> [x/2], odd x -> [x/2 + 1]
        sUVe[r][2 * g4]     = make_float2(u[0], v[0]);
        sUVo[r][2 * g4 + 1] = make_float2(u[1], v[1]);
        sUVe[r][2 * g4 + 1] = make_float2(u[2], v[2]);
        sUVo[r][2 * g4 + 2] = make_float2(u[3], v[3]);
    }
    __syncthreads();

    if (cwblk && t == 0) {
        g_invS2_4 = 0.25f / (s_cwsum[0] + s_cwsum[1] + s_cwsum[2] + s_cwsum[3]
                           + s_cwsum[4] + s_cwsum[5] + s_cwsum[6] + s_cwsum[7] + EPS);
    }

    const float scale = (1.0f / (wp + 1.0f)) * (1.0f / (s_S + EPS));

    // ---- spatial 3x3 stride-2 reduce (2 output pixels per thread) ----
    const int wo = t & 127;
    const int hb = t >> 7;            // 0 or 1
    #pragma unroll
    for (int it = 0; it < 2; ++it) {
        const int hloc = hb + it * 2;
        const int ho   = ho0 + hloc;
        float nom = 0.0f, den = 0.0f;
        const size_t spbase = (size_t)bc * KK * HWO + (size_t)ho * WOn + wo;
        #pragma unroll
        for (int i = 0; i < 3; i++) {
            const int r = 2 * hloc + i;
            const float sp0 = __ldcs(&sprod[spbase + (size_t)(i * 3 + 0) * HWO]);
            const float sp1 = __ldcs(&sprod[spbase + (size_t)(i * 3 + 1) * HWO]);
            const float sp2 = __ldcs(&sprod[spbase + (size_t)(i * 3 + 2) * HWO]);
            const float w0 = s_sw[i * 3 + 0] * sp0;   // x = 2wo-1 (odd)
            const float w1 = s_sw[i * 3 + 1] * sp1;   // x = 2wo   (even)
            const float w2 = s_sw[i * 3 + 2] * sp2;   // x = 2wo+1 (odd)
            const float2 a = sUVo[r][wo];
            const float2 b = sUVe[r][wo];
            const float2 d = sUVo[r][wo + 1];
            nom += w0 * a.x + w1 * b.x + w2 * d.x;
            den += w0 * a.y + w1 * b.y + w2 * d.y;
        }
        const size_t oidx = (size_t)bc * HWO + (size_t)ho * WOn + wo;
        g_PQ[oidx] = make_float2(nom * scale, den * scale);
    }
}

// -------- kernel 2: 1x1 channel mix, og-split across LANE PARITY --------
// Even lane: outputs 0-15; odd lane: outputs 16-31; lane pair shares one
// pixel so both lanes load the SAME PQ address -> LSU broadcast merges them:
// one 128B line per warp-load, PQ read exactly ONCE (16.8MB L2 traffic,
// half of the block-level og-split). Otherwise identical to the R12 winner.
__global__ __launch_bounds__(128) void channel_kernel(
    const float* __restrict__ bias, float* __restrict__ out)
{
    __shared__ ulonglong2 scw[Cn * 16];  // [cc][op 0..15] both og halves
    __shared__ float sbias[On];
    const int t = threadIdx.x;

    #pragma unroll
    for (int i = t; i < Cn * 16; i += 128) {
        const int cc = i >> 4, op = i & 15;
        scw[i] = make_ulonglong2(g_cw2[cc * On + 2 * op],
                                 g_cw2[cc * On + 2 * op + 1]);
    }
    if (t < On) sbias[t] = __ldg(&bias[t]);
    __syncthreads();
    const float invS2_4 = g_invS2_4;

    const int lane_og = t & 1;                   // output half for this lane
    const int og0     = lane_og * 16;
    const int px = (blockIdx.x * 128 + t) >> 1;  // lane pair shares pixel
    const int b  = px >> 14;                     // / HWO
    const int hw = px & (HWO - 1);

    const unsigned long long* PQ =
        (const unsigned long long*)g_PQ + (size_t)b * Cn * HWO + hw;

    unsigned long long acc[16];
    #pragma unroll
    for (int oo = 0; oo < 16; oo++) acc[oo] = 0ull;

    // software pipeline: chunk k+1 loads issue before chunk k is consumed
    unsigned long long cur[8], nxt[8];
    #pragma unroll
    for (int j = 0; j < 8; j++) cur[j] = PQ[(size_t)j * HWO];

    #pragma unroll
    for (int ccg = 0; ccg < Cn; ccg += 8) {
        if (ccg + 8 < Cn) {
            #pragma unroll
            for (int j = 0; j < 8; j++)
                nxt[j] = PQ[(size_t)(ccg + 8 + j) * HWO];
        }
        #pragma unroll
        for (int j = 0; j < 8; j++) {
            const unsigned long long p = cur[j];
            #pragma unroll
            for (int op = 0; op < 8; op++) {
                // lane-og-dependent half: 2 distinct LDS.128 addrs per warp
                const ulonglong2 ww = scw[(ccg + j) * 16 + lane_og * 8 + op];
                FMA2(acc[2 * op],     p, ww.x);
                FMA2(acc[2 * op + 1], p, ww.y);
            }
        }
        #pragma unroll
        for (int j = 0; j < 8; j++) cur[j] = nxt[j];
    }

    const size_t obase = (size_t)b * On * HWO + (size_t)og0 * HWO + hw;
    const size_t half  = (size_t)Bn * On * HWO;
    #pragma unroll
    for (int oo = 0; oo < 16; oo++) {
        const float n = __uint_as_float((unsigned)acc[oo]);
        const float d = __uint_as_float((unsigned)(acc[oo] >> 32));
        out[obase + (size_t)oo * HWO]        =
            (__fdividef(n, d + EPS) + sbias[og0 + oo]) * 2.0f;
        out[half + obase + (size_t)oo * HWO] = d * invS2_4;
    }
}

extern "C" void kernel_launch(void* const* d_in, const int* in_sizes, int n_in,
                              void* d_out, int out_size) {
    // metadata order: d, cd, s, cs, gx, cgx, s_prod_roll,
    //                 w_prop, spatial_weight, channel_weight, bias
    // (d and cs are provably unused — see stage1 simplification)
    const float* cd_p    = (const float*)d_in[1];
    const float* s_p     = (const float*)d_in[2];
    const float* gx_p    = (const float*)d_in[4];
    const float* cgx_p   = (const float*)d_in[5];
    const float* sprod_p = (const float*)d_in[6];
    const float* wprop_p = (const float*)d_in[7];
    const float* sw_p    = (const float*)d_in[8];
    const float* cw_p    = (const float*)d_in[9];
    const float* bias_p  = (const float*)d_in[10];

    dim3 gA(Bn * Cn, 32);            // bc-fast block order (best measured)
    spatial_kernel<<<gA, 256>>>(s_p, cd_p, gx_p, cgx_p, sprod_p,
                                wprop_p, sw_p, cw_p);

    // 65536 px x 2 og-lane-halves / 128 threads = 1024 blocks
    channel_kernel<<<1024, 128>>>(bias_p, (float*)d_out);
}

// round 17
// speedup vs baseline: 1.2615x; 1.1760x over previous
#include <cuda_runtime.h>
#include <cuda_fp16.h>
#include <math.h>

#define EPS 1e-20f
#define Bn 4
#define Cn 32
#define On 32
#define Hn 256
#define Wn 256
#define HOn 128
#define WOn 128
#define HWO (HOn*WOn)      /* 16384 */
#define KK 9
#define PQ_SCALE 4096.0f

// -------- device scratch (no allocations allowed) --------
__device__ __half2 g_PQh[Bn*Cn*HWO];          // (P,Q)*4096 as half2, 33.5MB
__device__ unsigned long long g_cw2[Cn*On];   // [c][o] softplus(cw) packed {w,w}
__device__ float g_invS2_4;                   // 0.25/(4096*(sum cw + eps))

__device__ __forceinline__ float softplusf(float x) {
    return fmaxf(x, 0.0f) + log1pf(expf(-fabsf(x)));
}

// packed f32x2 FMA (sm_103a FFMA2 — only reachable via PTX)
#define FMA2(acc, a, b) \
    asm("fma.rn.f32x2 %0, %1, %2, %3;" : "=l"(acc) : "l"(a), "l"(b), "l"(acc))

// -------- kernel 1: stage1 + spatial (per (b,c), 4 output rows per block) --------
// (R7 structure — best measured; only the PQ store is now half2*4096)
// Stage1 exact simplification (reference's pad_r/pad_l are edge-zero masks):
//   cgx_from_ds = s^3 * cd^2 for 0<x<W-1, else 0;  gx_from_ds term contributes 0.
//   U = wp*cgx*gx ;  V = wp*cgx + cgx_from_ds
// Spatial: nom = sum_k sw_k*sprod_k*U_k/(wp+1);  den = sum_k sw_k*sprod_k*V_k/(wp+1)
//   P = nom/(S+eps) ;  Q = den/(S+eps)    (both stored x4096 in fp16)
__global__ __launch_bounds__(256) void spatial_kernel(
    const float* __restrict__ s_in, const float* __restrict__ cd,
    const float* __restrict__ gx,   const float* __restrict__ cgx,
    const float* __restrict__ sprod,
    const float* __restrict__ w_prop, const float* __restrict__ spatial_weight,
    const float* __restrict__ channel_weight)
{
    // parity-split tile, U,V packed: taps (2wo-1, 2wo, 2wo+1) -> odd[wo], even[wo], odd[wo+1]
    __shared__ float2 sUVe[9][128];
    __shared__ float2 sUVo[9][132];   // [0] = zero pad (x = -1)
    __shared__ float  s_sw[KK];
    __shared__ float  s_S;
    __shared__ float  s_cwsum[8];

    const int bc  = blockIdx.x;          // b*Cn + c
    const int c   = bc & (Cn - 1);
    const int ho0 = blockIdx.y * 4;
    const int ir0 = 2 * ho0 - 1;
    const int t   = threadIdx.x;

    const float wp = softplusf(__ldg(&w_prop[c]));

    // warp 0: sum of all 288 softplus(spatial_weight) via shuffle
    if (t < 32) {
        float acc = 0.0f;
        #pragma unroll
        for (int k = 0; k < KK; k++)
            acc += softplusf(__ldg(&spatial_weight[t * KK + k]));
        #pragma unroll
        for (int off = 16; off > 0; off >>= 1)
            acc += __shfl_xor_sync(0xffffffffu, acc, off);
        if (t == 0) s_S = acc;
    }
    if (t >= 32 && t < 32 + KK)
        s_sw[t - 32] = softplusf(__ldg(&spatial_weight[c * KK + (t - 32)]));
    if (t >= 64 && t < 64 + 9)
        sUVo[t - 64][0] = make_float2(0.0f, 0.0f);

    // block (0,0) additionally pre-packs channel weights for the channel kernel
    const bool cwblk = (blockIdx.x == 0) && (blockIdx.y == 0);
    if (cwblk) {
        float partial = 0.0f;
        #pragma unroll
        for (int i = t; i < Cn * On; i += 256) {
            const int o = i >> 5, cc = i & 31;
            const float w = softplusf(__ldg(&channel_weight[i]));  // i = o*Cn + cc
            const unsigned wu = __float_as_uint(w);
            g_cw2[cc * On + o] = ((unsigned long long)wu << 32) | wu;
            partial += w;
        }
        #pragma unroll
        for (int off = 16; off > 0; off >>= 1)
            partial += __shfl_xor_sync(0xffffffffu, partial, off);
        if ((t & 31) == 0) s_cwsum[t >> 5] = partial;
    }

    const size_t plane = (size_t)bc * (Hn * Wn);

    // ---- stage U,V for 9 input rows x 256 cols (float4-coalesced, streaming) ----
    for (int idx = t; idx < 9 * 64; idx += 256) {
        const int r  = idx >> 6;
        const int g4 = idx & 63;
        const int ir = ir0 + r;
        float u[4], v[4];
        if (ir >= 0 && ir < Hn) {
            const size_t base = plane + (size_t)ir * Wn + g4 * 4;
            const float4 sx  = __ldcs((const float4*)(s_in + base));
            const float4 cdx = __ldcs((const float4*)(cd   + base));
            const float4 gxx = __ldcs((const float4*)(gx   + base));
            const float4 cgv = __ldcs((const float4*)(cgx  + base));
            const float se[4]  = {sx.x,  sx.y,  sx.z,  sx.w};
            const float cde[4] = {cdx.x, cdx.y, cdx.z, cdx.w};
            const float ge[4]  = {gxx.x, gxx.y, gxx.z, gxx.w};
            const float cge[4] = {cgv.x, cgv.y, cgv.z, cgv.w};
            #pragma unroll
            for (int e = 0; e < 4; e++) {
                const int x = g4 * 4 + e;
                const float cgds = (x == 0 || x == Wn - 1)
                                 ? 0.0f
                                 : se[e] * se[e] * se[e] * cde[e] * cde[e];
                u[e] = wp * cge[e] * ge[e];
                v[e] = wp * cge[e] + cgds;
            }
        } else {
            #pragma unroll
            for (int e = 0; e < 4; e++) { u[e] = 0.0f; v[e] = 0.0f; }
        }
        // parity-split store: even x -> [x/2], odd x -> [x/2 + 1]
        sUVe[r][2 * g4]     = make_float2(u[0], v[0]);
        sUVo[r][2 * g4 + 1] = make_float2(u[1], v[1]);
        sUVe[r][2 * g4 + 1] = make_float2(u[2], v[2]);
        sUVo[r][2 * g4 + 2] = make_float2(u[3], v[3]);
    }
    __syncthreads();

    if (cwblk && t == 0) {
        g_invS2_4 = (0.25f / PQ_SCALE)
                  / (s_cwsum[0] + s_cwsum[1] + s_cwsum[2] + s_cwsum[3]
                   + s_cwsum[4] + s_cwsum[5] + s_cwsum[6] + s_cwsum[7] + EPS);
    }

    const float scale = (1.0f / (wp + 1.0f)) * (1.0f / (s_S + EPS)) * PQ_SCALE;

    // ---- spatial 3x3 stride-2 reduce (2 output pixels per thread) ----
    const int wo = t & 127;
    const int hb = t >> 7;            // 0 or 1
    #pragma unroll
    for (int it = 0; it < 2; ++it) {
        const int hloc = hb + it * 2;
        const int ho   = ho0 + hloc;
        float nom = 0.0f, den = 0.0f;
        const size_t spbase = (size_t)bc * KK * HWO + (size_t)ho * WOn + wo;
        #pragma unroll
        for (int i = 0; i < 3; i++) {
            const int r = 2 * hloc + i;
            const float sp0 = __ldcs(&sprod[spbase + (size_t)(i * 3 + 0) * HWO]);
            const float sp1 = __ldcs(&sprod[spbase + (size_t)(i * 3 + 1) * HWO]);
            const float sp2 = __ldcs(&sprod[spbase + (size_t)(i * 3 + 2) * HWO]);
            const float w0 = s_sw[i * 3 + 0] * sp0;   // x = 2wo-1 (odd)
            const float w1 = s_sw[i * 3 + 1] * sp1;   // x = 2wo   (even)
            const float w2 = s_sw[i * 3 + 2] * sp2;   // x = 2wo+1 (odd)
            const float2 a = sUVo[r][wo];
            const float2 b = sUVe[r][wo];
            const float2 d = sUVo[r][wo + 1];
            nom += w0 * a.x + w1 * b.x + w2 * d.x;
            den += w0 * a.y + w1 * b.y + w2 * d.y;
        }
        const size_t oidx = (size_t)bc * HWO + (size_t)ho * WOn + wo;
        g_PQh[oidx] = __floats2half2_rn(nom * scale, den * scale);
    }
}

// -------- kernel 2: 1x1 channel mix; 1 pixel x 16 outputs per thread --------
// (R12 structure — best measured) og-split 2, 128-thread blocks, LDS.128
// weight pairs, chunk-8 pipeline. PQ now half2: warp loads are 128B (one
// wavefront, was two), PQ read traffic halves.
__global__ __launch_bounds__(128) void channel_kernel(
    const float* __restrict__ bias, float* __restrict__ out)
{
    __shared__ ulonglong2 scw[Cn * 8];   // [cc][op], 2 packed weights per entry
    __shared__ float sbias[16];
    const int t   = threadIdx.x;
    const int og0 = (blockIdx.x & 1) * 16;       // og half: low bit -> L2 locality

    #pragma unroll
    for (int i = t; i < Cn * 8; i += 128) {
        const int cc = i >> 3, op = i & 7;
        scw[i] = make_ulonglong2(g_cw2[cc * On + og0 + 2 * op],
                                 g_cw2[cc * On + og0 + 2 * op + 1]);
    }
    if (t < 16) sbias[t] = __ldg(&bias[og0 + t]);
    __syncthreads();
    const float invS2_4 = g_invS2_4;

    const int px = (blockIdx.x >> 1) * 128 + t;
    const int b  = px >> 14;             // / HWO
    const int hw = px & (HWO - 1);

    const __half2* PQ = g_PQh + (size_t)b * Cn * HWO + hw;

    unsigned long long acc[16];
    #pragma unroll
    for (int oo = 0; oo < 16; oo++) acc[oo] = 0ull;

    // software pipeline: chunk k+1 loads issue before chunk k is consumed
    __half2 cur[8], nxt[8];
    #pragma unroll
    for (int j = 0; j < 8; j++) cur[j] = PQ[(size_t)j * HWO];

    #pragma unroll
    for (int ccg = 0; ccg < Cn; ccg += 8) {
        if (ccg + 8 < Cn) {
            #pragma unroll
            for (int j = 0; j < 8; j++)
                nxt[j] = PQ[(size_t)(ccg + 8 + j) * HWO];
        }
        #pragma unroll
        for (int j = 0; j < 8; j++) {
            const float2 f = __half22float2(cur[j]);
            unsigned long long p;
            asm("mov.b64 %0, {%1, %2};" : "=l"(p)
                : "r"(__float_as_uint(f.x)), "r"(__float_as_uint(f.y)));
            #pragma unroll
            for (int op = 0; op < 8; op++) {
                const ulonglong2 ww = scw[(ccg + j) * 8 + op];   // LDS.128 broadcast
                FMA2(acc[2 * op],     p, ww.x);
                FMA2(acc[2 * op + 1], p, ww.y);
            }
        }
        #pragma unroll
        for (int j = 0; j < 8; j++) cur[j] = nxt[j];
    }

    const size_t obase = (size_t)b * On * HWO + (size_t)og0 * HWO + hw;
    const size_t half  = (size_t)Bn * On * HWO;
    #pragma unroll
    for (int oo = 0; oo < 16; oo++) {
        const float n = __uint_as_float((unsigned)acc[oo]);
        const float d = __uint_as_float((unsigned)(acc[oo] >> 32));
        out[obase + (size_t)oo * HWO]        =
            (__fdividef(n, d + EPS) + sbias[oo]) * 2.0f;
        out[half + obase + (size_t)oo * HWO] = d * invS2_4;
    }
}

extern "C" void kernel_launch(void* const* d_in, const int* in_sizes, int n_in,
                              void* d_out, int out_size) {
    // metadata order: d, cd, s, cs, gx, cgx, s_prod_roll,
    //                 w_prop, spatial_weight, channel_weight, bias
    // (d and cs are provably unused — see stage1 simplification)
    const float* cd_p    = (const float*)d_in[1];
    const float* s_p     = (const float*)d_in[2];
    const float* gx_p    = (const float*)d_in[4];
    const float* cgx_p   = (const float*)d_in[5];
    const float* sprod_p = (const float*)d_in[6];
    const float* wprop_p = (const float*)d_in[7];
    const float* sw_p    = (const float*)d_in[8];
    const float* cw_p    = (const float*)d_in[9];
    const float* bias_p  = (const float*)d_in[10];

    dim3 gA(Bn * Cn, 32);            // bc-fast block order (best measured)
    spatial_kernel<<<gA, 256>>>(s_p, cd_p, gx_p, cgx_p, sprod_p,
                                wprop_p, sw_p, cw_p);

    // 65536 pixels x 2 og-halves / 128 threads = 1024 blocks
    channel_kernel<<<1024, 128>>>(bias_p, (float*)d_out);
}